// round 2
// baseline (speedup 1.0000x reference)
#include <cuda_runtime.h>
#include <math.h>

#define Dm 1024
#define Hh 16
#define HDm 64
#define FFm 4096
#define BATCHm 8
#define SEQm 1024
#define TOKm (BATCHm*SEQm)   /* 8192 */
#define BHm (BATCHm*Hh)      /* 128  */

static __device__ float g_h   [(size_t)TOKm*Dm];        // LN outputs (reused)
static __device__ float g_qkv [(size_t)TOKm*3*Dm];      // qkv gemm out
static __device__ float g_q   [(size_t)BHm*SEQm*HDm];
static __device__ float g_k   [(size_t)BHm*SEQm*HDm];
static __device__ float g_v   [(size_t)BHm*SEQm*HDm];
static __device__ float g_s   [(size_t)BHm*SEQm*SEQm];  // 537 MB scores
static __device__ float g_o   [(size_t)TOKm*Dm];        // attn output [b,t,h,hd]
static __device__ float g_x1  [(size_t)TOKm*Dm];        // after attn residual
static __device__ float g_g   [(size_t)TOKm*FFm];       // gelu(fc1) out

// ---------------------------------------------------------------------------
// LayerNorm: one block per row (D=1024), 256 threads.
// ---------------------------------------------------------------------------
__global__ void ln_kernel(const float* __restrict__ x,
                          const float* __restrict__ gam,
                          const float* __restrict__ bet,
                          float* __restrict__ out)
{
    const float* xr = x + (size_t)blockIdx.x * Dm;
    float* orow     = out + (size_t)blockIdx.x * Dm;
    int tid = threadIdx.x;

    float s = 0.f, s2 = 0.f;
    for (int i = tid; i < Dm; i += 256) {
        float v = xr[i];
        s += v; s2 += v * v;
    }
    __shared__ float rs[8], rs2[8];
    #pragma unroll
    for (int o = 16; o > 0; o >>= 1) {
        s  += __shfl_xor_sync(0xffffffffu, s,  o);
        s2 += __shfl_xor_sync(0xffffffffu, s2, o);
    }
    if ((tid & 31) == 0) { rs[tid >> 5] = s; rs2[tid >> 5] = s2; }
    __syncthreads();
    if (tid < 32) {
        float a = (tid < 8) ? rs[tid]  : 0.f;
        float b = (tid < 8) ? rs2[tid] : 0.f;
        #pragma unroll
        for (int o = 4; o > 0; o >>= 1) {
            a += __shfl_xor_sync(0xffffffffu, a, o);
            b += __shfl_xor_sync(0xffffffffu, b, o);
        }
        if (tid == 0) { rs[0] = a; rs2[0] = b; }
    }
    __syncthreads();
    float mu  = rs[0] * (1.0f / Dm);
    float var = rs2[0] * (1.0f / Dm) - mu * mu;
    float inv = rsqrtf(var + 1e-5f);
    for (int i = tid; i < Dm; i += 256)
        orow[i] = (xr[i] - mu) * inv * gam[i] + bet[i];
}

// ---------------------------------------------------------------------------
// QKV scatter: read [8192,3072] gemm out, add biases, fold q scale (1/8),
// write q/k/v in [B,H,N,HD] contiguous layout.
// ---------------------------------------------------------------------------
__global__ void qkv_scatter(const float* __restrict__ qkv,
                            const float* __restrict__ qb,
                            const float* __restrict__ vb)
{
    size_t idx = (size_t)blockIdx.x * blockDim.x + threadIdx.x;
    if (idx >= (size_t)TOKm * 3 * Dm) return;
    int    n = (int)(idx % (3 * Dm));
    size_t m = idx / (3 * Dm);
    int which = n / Dm;
    int r = n % Dm;
    int h = r / HDm, hd = r % HDm;
    int b = (int)(m / SEQm), t = (int)(m % SEQm);
    size_t dst = (((size_t)b * Hh + h) * SEQm + t) * HDm + hd;
    float val = qkv[idx];
    if (which == 0)      g_q[dst] = (val + qb[r]) * 0.125f;   // scale = 64^-0.5
    else if (which == 1) g_k[dst] = val;
    else                 g_v[dst] = val + vb[r];
}

// ---------------------------------------------------------------------------
// Row softmax over scores: one block per row of length SEQ.
// ---------------------------------------------------------------------------
__global__ void softmax_kernel(float* __restrict__ S)
{
    float* r = S + (size_t)blockIdx.x * SEQm;
    int tid = threadIdx.x;
    __shared__ float red[8];

    float m = -3.4e38f;
    for (int i = tid; i < SEQm; i += 256) m = fmaxf(m, r[i]);
    #pragma unroll
    for (int o = 16; o > 0; o >>= 1) m = fmaxf(m, __shfl_xor_sync(0xffffffffu, m, o));
    if ((tid & 31) == 0) red[tid >> 5] = m;
    __syncthreads();
    if (tid < 32) {
        float v = (tid < 8) ? red[tid] : -3.4e38f;
        #pragma unroll
        for (int o = 4; o > 0; o >>= 1) v = fmaxf(v, __shfl_xor_sync(0xffffffffu, v, o));
        if (tid == 0) red[0] = v;
    }
    __syncthreads();
    float M = red[0];
    __syncthreads();

    float s = 0.f;
    for (int i = tid; i < SEQm; i += 256) {
        float e = expf(r[i] - M);
        r[i] = e; s += e;
    }
    #pragma unroll
    for (int o = 16; o > 0; o >>= 1) s += __shfl_xor_sync(0xffffffffu, s, o);
    if ((tid & 31) == 0) red[tid >> 5] = s;
    __syncthreads();
    if (tid < 32) {
        float v = (tid < 8) ? red[tid] : 0.f;
        #pragma unroll
        for (int o = 4; o > 0; o >>= 1) v += __shfl_xor_sync(0xffffffffu, v, o);
        if (tid == 0) red[0] = v;
    }
    __syncthreads();
    float inv = 1.f / red[0];
    for (int i = tid; i < SEQm; i += 256) r[i] *= inv;
}

// ---------------------------------------------------------------------------
// Templated SGEMM. C[M,N] = A[M,K] * op(B) with op = B^T (TB) or B (NN).
// A row-major lda=K; TB: B row-major [N,K]; NN: B row-major [K,N].
// Batched via blockIdx.z with element strides bA/bB/bC.
// EPI: 0 plain, 2 bias+residual, 3 bias+exact-gelu, 4 attn-O scatter store.
// All problem dims must divide the tile sizes (true for every call below).
// ---------------------------------------------------------------------------
template<int BM, int BN, int BK, int TM, int TN, bool TB, int EPI>
__global__ __launch_bounds__((BM/TM)*(BN/TN))
void gemm_kernel(const float* __restrict__ A, const float* __restrict__ Bm,
                 float* __restrict__ C, int M, int N, int K,
                 long bA, long bB, long bC,
                 const float* __restrict__ bias,
                 const float* __restrict__ res)
{
    constexpr int TX = BN / TN, TY = BM / TM, NT = TX * TY;
    __shared__ float As[BK][BM + 4];
    __shared__ float Bs[BK][BN + 4];

    int tid = threadIdx.x;
    int tx = tid % TX, ty = tid / TX;
    int m0 = blockIdx.y * BM, n0 = blockIdx.x * BN;
    long z = blockIdx.z;
    const float* Ab = A  + z * bA;
    const float* Bb = Bm + z * bB;

    float acc[TM][TN];
    #pragma unroll
    for (int i = 0; i < TM; i++)
        #pragma unroll
        for (int j = 0; j < TN; j++) acc[i][j] = 0.f;

    for (int k0 = 0; k0 < K; k0 += BK) {
        // --- load A tile (BM x BK), store k-major into As ---
        constexpr int A4 = BM * BK / 4;
        #pragma unroll
        for (int i = tid; i < A4; i += NT) {
            int rrow = i / (BK / 4);
            int c4   = i % (BK / 4);
            float4 vv = *(const float4*)(Ab + (size_t)(m0 + rrow) * K + k0 + c4 * 4);
            As[c4 * 4 + 0][rrow] = vv.x;
            As[c4 * 4 + 1][rrow] = vv.y;
            As[c4 * 4 + 2][rrow] = vv.z;
            As[c4 * 4 + 3][rrow] = vv.w;
        }
        // --- load B tile ---
        if (TB) {
            constexpr int B4 = BN * BK / 4;
            #pragma unroll
            for (int i = tid; i < B4; i += NT) {
                int rrow = i / (BK / 4);
                int c4   = i % (BK / 4);
                float4 vv = *(const float4*)(Bb + (size_t)(n0 + rrow) * K + k0 + c4 * 4);
                Bs[c4 * 4 + 0][rrow] = vv.x;
                Bs[c4 * 4 + 1][rrow] = vv.y;
                Bs[c4 * 4 + 2][rrow] = vv.z;
                Bs[c4 * 4 + 3][rrow] = vv.w;
            }
        } else {
            constexpr int B4 = BN * BK / 4;
            #pragma unroll
            for (int i = tid; i < B4; i += NT) {
                int rrow = i / (BN / 4);
                int c4   = i % (BN / 4);
                float4 vv = *(const float4*)(Bb + (size_t)(k0 + rrow) * N + n0 + c4 * 4);
                *(float4*)&Bs[rrow][c4 * 4] = vv;
            }
        }
        __syncthreads();

        #pragma unroll
        for (int kk = 0; kk < BK; kk++) {
            float a[TM], b[TN];
            const float* arow = &As[kk][ty * TM];
            const float* brow = &Bs[kk][tx * TN];
            #pragma unroll
            for (int i = 0; i < TM; i += 4) {
                float4 t4 = *(const float4*)(arow + i);
                a[i] = t4.x; a[i+1] = t4.y; a[i+2] = t4.z; a[i+3] = t4.w;
            }
            #pragma unroll
            for (int j = 0; j < TN; j += 4) {
                float4 t4 = *(const float4*)(brow + j);
                b[j] = t4.x; b[j+1] = t4.y; b[j+2] = t4.z; b[j+3] = t4.w;
            }
            #pragma unroll
            for (int i = 0; i < TM; i++)
                #pragma unroll
                for (int j = 0; j < TN; j++)
                    acc[i][j] = fmaf(a[i], b[j], acc[i][j]);
        }
        __syncthreads();
    }

    // --- epilogue ---
    #pragma unroll
    for (int i = 0; i < TM; i++) {
        int m = m0 + ty * TM + i;
        #pragma unroll
        for (int j = 0; j < TN; j++) {
            int n = n0 + tx * TN + j;
            float v = acc[i][j];
            if (EPI == 2 || EPI == 3) v += bias[n];
            if (EPI == 2) v += res[(size_t)m * N + n];
            if (EPI == 3) v = 0.5f * v * (1.f + erff(v * 0.70710678118654752f));
            if (EPI == 4) {
                int bb = (int)(z / Hh), hh = (int)(z % Hh);
                C[((size_t)bb * SEQm + m) * Dm + hh * HDm + n] = v;
            } else {
                C[z * bC + (size_t)m * N + n] = v;
            }
        }
    }
}

// ---------------------------------------------------------------------------
extern "C" void kernel_launch(void* const* d_in, const int* in_sizes, int n_in,
                              void* d_out, int out_size)
{
    const float* x      = (const float*)d_in[0];
    const float* ln1_g  = (const float*)d_in[1];
    const float* ln1_b  = (const float*)d_in[2];
    const float* ln2_g  = (const float*)d_in[3];
    const float* ln2_b  = (const float*)d_in[4];
    const float* qkv_w  = (const float*)d_in[5];
    const float* q_bias = (const float*)d_in[6];
    const float* v_bias = (const float*)d_in[7];
    const float* proj_w = (const float*)d_in[8];
    const float* proj_b = (const float*)d_in[9];
    const float* fc1_w  = (const float*)d_in[10];
    const float* fc1_b  = (const float*)d_in[11];
    const float* fc2_w  = (const float*)d_in[12];
    const float* fc2_b  = (const float*)d_in[13];
    float* out = (float*)d_out;

    float *h, *qkv, *q, *k, *v, *s, *o, *x1, *g;
    cudaGetSymbolAddress((void**)&h,   g_h);
    cudaGetSymbolAddress((void**)&qkv, g_qkv);
    cudaGetSymbolAddress((void**)&q,   g_q);
    cudaGetSymbolAddress((void**)&k,   g_k);
    cudaGetSymbolAddress((void**)&v,   g_v);
    cudaGetSymbolAddress((void**)&s,   g_s);
    cudaGetSymbolAddress((void**)&o,   g_o);
    cudaGetSymbolAddress((void**)&x1,  g_x1);
    cudaGetSymbolAddress((void**)&g,   g_g);

    // 1. LN1
    ln_kernel<<<TOKm, 256>>>(x, ln1_g, ln1_b, h);

    // 2. QKV = h @ qkv_w^T   [8192,3072]
    gemm_kernel<128,128,16,8,8,true,0><<<dim3(3072/128, TOKm/128, 1), 256>>>(
        h, qkv_w, qkv, TOKm, 3*Dm, Dm, 0, 0, 0, nullptr, nullptr);

    // 3. scatter to q/k/v [B,H,N,HD], fold biases + q scale
    {
        size_t total = (size_t)TOKm * 3 * Dm;
        qkv_scatter<<<(unsigned)((total + 255) / 256), 256>>>(qkv, q_bias, v_bias);
    }

    // 4. scores[bh] = q[bh] @ k[bh]^T   128 x [1024,1024], K=64
    gemm_kernel<128,128,16,8,8,true,0><<<dim3(SEQm/128, SEQm/128, BHm), 256>>>(
        q, k, s, SEQm, SEQm, HDm,
        (long)SEQm*HDm, (long)SEQm*HDm, (long)SEQm*SEQm, nullptr, nullptr);

    // 5. softmax rows
    softmax_kernel<<<BHm * SEQm, 256>>>(s);

    // 6. o[bh] = attn[bh] @ v[bh]   (NN, N=64), scatter store to [b,t,h,hd]
    gemm_kernel<128,64,16,8,4,false,4><<<dim3(1, SEQm/128, BHm), 256>>>(
        s, v, o, SEQm, HDm, SEQm,
        (long)SEQm*SEQm, (long)SEQm*HDm, 0, nullptr, nullptr);

    // 7. x1 = x + o @ proj_w^T + proj_b
    gemm_kernel<128,128,16,8,8,true,2><<<dim3(Dm/128, TOKm/128, 1), 256>>>(
        o, proj_w, x1, TOKm, Dm, Dm, 0, 0, 0, proj_b, x);

    // 8. LN2
    ln_kernel<<<TOKm, 256>>>(x1, ln2_g, ln2_b, h);

    // 9. g = gelu(h @ fc1_w^T + fc1_b)   [8192,4096]
    gemm_kernel<128,128,16,8,8,true,3><<<dim3(FFm/128, TOKm/128, 1), 256>>>(
        h, fc1_w, g, TOKm, FFm, Dm, 0, 0, 0, fc1_b, nullptr);

    // 10. out = x1 + g @ fc2_w^T + fc2_b
    gemm_kernel<128,128,16,8,8,true,2><<<dim3(Dm/128, TOKm/128, 1), 256>>>(
        g, fc2_w, out, TOKm, Dm, FFm, 0, 0, 0, fc2_b, x1);
}

// round 3
// speedup vs baseline: 2.4683x; 2.4683x over previous
#include <cuda_runtime.h>
#include <math.h>
#include <stdint.h>

#define Dm 1024
#define Hh 16
#define HDm 64
#define FFm 4096
#define BATCHm 8
#define SEQm 1024
#define TOKm (BATCHm*SEQm)   /* 8192 */
#define BHm (BATCHm*Hh)      /* 128  */

static __device__ float g_h   [(size_t)TOKm*Dm];        // LN outputs (reused)
static __device__ float g_q   [(size_t)BHm*SEQm*HDm];
static __device__ float g_k   [(size_t)BHm*SEQm*HDm];
static __device__ float g_v   [(size_t)BHm*SEQm*HDm];
static __device__ float g_s   [(size_t)BHm*SEQm*SEQm];  // 537 MB scores
static __device__ float g_o   [(size_t)TOKm*Dm];        // attn output [b,t,h,hd]
static __device__ float g_x1  [(size_t)TOKm*Dm];        // after attn residual
static __device__ float g_g   [(size_t)TOKm*FFm];       // gelu(fc1) out

// ---------------------------------------------------------------------------
// helpers
// ---------------------------------------------------------------------------
__device__ __forceinline__ uint32_t f2tf32(float f) {
    uint32_t r;
    asm("cvt.rna.tf32.f32 %0, %1;" : "=r"(r) : "f"(f));
    return r;
}
__device__ __forceinline__ void cp16(uint32_t dst, const void* src) {
    asm volatile("cp.async.cg.shared.global [%0], [%1], 16;" :: "r"(dst), "l"(src));
}
__device__ __forceinline__ void mma_tf32(float* c, const uint32_t* a, const uint32_t* b) {
    asm volatile(
        "mma.sync.aligned.m16n8k8.row.col.f32.tf32.tf32.f32 "
        "{%0,%1,%2,%3},{%4,%5,%6,%7},{%8,%9},{%0,%1,%2,%3};"
        : "+f"(c[0]), "+f"(c[1]), "+f"(c[2]), "+f"(c[3])
        : "r"(a[0]), "r"(a[1]), "r"(a[2]), "r"(a[3]), "r"(b[0]), "r"(b[1]));
}

// ---------------------------------------------------------------------------
// LayerNorm: one block per row (D=1024), 256 threads.
// ---------------------------------------------------------------------------
__global__ void ln_kernel(const float* __restrict__ x,
                          const float* __restrict__ gam,
                          const float* __restrict__ bet,
                          float* __restrict__ out)
{
    const float* xr = x + (size_t)blockIdx.x * Dm;
    float* orow     = out + (size_t)blockIdx.x * Dm;
    int tid = threadIdx.x;

    float s = 0.f, s2 = 0.f;
    for (int i = tid; i < Dm; i += 256) {
        float v = xr[i];
        s += v; s2 += v * v;
    }
    __shared__ float rs[8], rs2[8];
    #pragma unroll
    for (int o = 16; o > 0; o >>= 1) {
        s  += __shfl_xor_sync(0xffffffffu, s,  o);
        s2 += __shfl_xor_sync(0xffffffffu, s2, o);
    }
    if ((tid & 31) == 0) { rs[tid >> 5] = s; rs2[tid >> 5] = s2; }
    __syncthreads();
    if (tid < 32) {
        float a = (tid < 8) ? rs[tid]  : 0.f;
        float b = (tid < 8) ? rs2[tid] : 0.f;
        #pragma unroll
        for (int o = 4; o > 0; o >>= 1) {
            a += __shfl_xor_sync(0xffffffffu, a, o);
            b += __shfl_xor_sync(0xffffffffu, b, o);
        }
        if (tid == 0) { rs[0] = a; rs2[0] = b; }
    }
    __syncthreads();
    float mu  = rs[0] * (1.0f / Dm);
    float var = rs2[0] * (1.0f / Dm) - mu * mu;
    float inv = rsqrtf(var + 1e-5f);
    for (int i = tid; i < Dm; i += 256)
        orow[i] = (xr[i] - mu) * inv * gam[i] + bet[i];
}

// ---------------------------------------------------------------------------
// Row softmax over scores: one block per row of length SEQ.
// ---------------------------------------------------------------------------
__global__ void softmax_kernel(float* __restrict__ S)
{
    float* r = S + (size_t)blockIdx.x * SEQm;
    int tid = threadIdx.x;
    __shared__ float red[8];

    float m = -3.4e38f;
    for (int i = tid; i < SEQm; i += 256) m = fmaxf(m, r[i]);
    #pragma unroll
    for (int o = 16; o > 0; o >>= 1) m = fmaxf(m, __shfl_xor_sync(0xffffffffu, m, o));
    if ((tid & 31) == 0) red[tid >> 5] = m;
    __syncthreads();
    if (tid < 32) {
        float v = (tid < 8) ? red[tid] : -3.4e38f;
        #pragma unroll
        for (int o = 4; o > 0; o >>= 1) v = fmaxf(v, __shfl_xor_sync(0xffffffffu, v, o));
        if (tid == 0) red[0] = v;
    }
    __syncthreads();
    float M = red[0];
    __syncthreads();

    float s = 0.f;
    for (int i = tid; i < SEQm; i += 256) {
        float e = expf(r[i] - M);
        r[i] = e; s += e;
    }
    #pragma unroll
    for (int o = 16; o > 0; o >>= 1) s += __shfl_xor_sync(0xffffffffu, s, o);
    if ((tid & 31) == 0) red[tid >> 5] = s;
    __syncthreads();
    if (tid < 32) {
        float v = (tid < 8) ? red[tid] : 0.f;
        #pragma unroll
        for (int o = 4; o > 0; o >>= 1) v += __shfl_xor_sync(0xffffffffu, v, o);
        if (tid == 0) red[0] = v;
    }
    __syncthreads();
    float inv = 1.f / red[0];
    for (int i = tid; i < SEQm; i += 256) r[i] *= inv;
}

// ---------------------------------------------------------------------------
// tf32 tensor-core GEMM, cp.async double-buffered.
// C[M,N] = A[M,K] * op(B); TB: B row-major [N,K]; else B row-major [K,N].
// Batched via blockIdx.z with element strides bA/bB/bC.
// EPI: 0 plain store, 2 bias+residual, 3 bias+exact-gelu,
//      4 attn-O scatter store to [b,t,h,hd], 5 qkv scatter (bias=qb, res=vb).
// ---------------------------------------------------------------------------
template<int BM, int BN, int BK, int WM, int WN, bool TB, int EPI>
__global__ __launch_bounds__((BM/WM)*(BN/WN)*32)
void tgemm(const float* __restrict__ A, const float* __restrict__ B,
           float* __restrict__ C, int M, int N, int K,
           long bA, long bB, long bC,
           const float* __restrict__ bias, const float* __restrict__ res)
{
    constexpr int WARPS_M = BM / WM, WARPS_N = BN / WN;
    constexpr int NT = WARPS_M * WARPS_N * 32;
    constexpr int MI = WM / 16, NI = WN / 8, KI = BK / 8;
    constexpr int BKP = BK + 4, BNP = BN + 4;
    constexpr int BROWS = TB ? BN : BK;
    constexpr int BCOLS = TB ? BKP : BNP;

    __shared__ float As[2][BM][BKP];
    __shared__ float Bs[2][BROWS][BCOLS];

    int tid = threadIdx.x, lane = tid & 31, warp = tid >> 5;
    int wm = (warp % WARPS_M) * WM, wn = (warp / WARPS_M) * WN;
    int m0 = blockIdx.y * BM, n0 = blockIdx.x * BN;
    long z = blockIdx.z;
    const float* Ab = A + z * bA;
    const float* Bb = B + z * bB;

    uint32_t sA = (uint32_t)__cvta_generic_to_shared(&As[0][0][0]);
    uint32_t sB = (uint32_t)__cvta_generic_to_shared(&Bs[0][0][0]);

    auto loadTile = [&](int st, int k0) {
        for (int i = tid; i < BM * BK / 4; i += NT) {
            int r = i / (BK / 4), c = i % (BK / 4);
            uint32_t dst = sA + (uint32_t)(((st * BM + r) * BKP + c * 4) * 4);
            cp16(dst, Ab + (size_t)(m0 + r) * K + k0 + c * 4);
        }
        if (TB) {
            for (int i = tid; i < BN * BK / 4; i += NT) {
                int r = i / (BK / 4), c = i % (BK / 4);
                uint32_t dst = sB + (uint32_t)(((st * BROWS + r) * BCOLS + c * 4) * 4);
                cp16(dst, Bb + (size_t)(n0 + r) * K + k0 + c * 4);
            }
        } else {
            for (int i = tid; i < BK * BN / 4; i += NT) {
                int r = i / (BN / 4), c = i % (BN / 4);
                uint32_t dst = sB + (uint32_t)(((st * BROWS + r) * BCOLS + c * 4) * 4);
                cp16(dst, Bb + (size_t)(k0 + r) * N + n0 + c * 4);
            }
        }
        asm volatile("cp.async.commit_group;");
    };

    float acc[MI][NI][4] = {};
    int g = lane >> 2, tg = lane & 3;

    loadTile(0, 0);
    int NKT = K / BK;
    for (int kt = 0; kt < NKT; kt++) {
        int cur = kt & 1;
        if (kt + 1 < NKT) {
            loadTile((kt + 1) & 1, (kt + 1) * BK);
            asm volatile("cp.async.wait_group 1;");
        } else {
            asm volatile("cp.async.wait_group 0;");
        }
        __syncthreads();

        #pragma unroll
        for (int kk = 0; kk < KI; kk++) {
            uint32_t af[MI][4];
            uint32_t bf[NI][2];
            #pragma unroll
            for (int mi = 0; mi < MI; mi++) {
                int r0 = wm + mi * 16 + g;
                af[mi][0] = f2tf32(As[cur][r0    ][kk * 8 + tg    ]);
                af[mi][1] = f2tf32(As[cur][r0 + 8][kk * 8 + tg    ]);
                af[mi][2] = f2tf32(As[cur][r0    ][kk * 8 + tg + 4]);
                af[mi][3] = f2tf32(As[cur][r0 + 8][kk * 8 + tg + 4]);
            }
            #pragma unroll
            for (int ni = 0; ni < NI; ni++) {
                int cc = wn + ni * 8 + g;
                if (TB) {
                    bf[ni][0] = f2tf32(Bs[cur][cc][kk * 8 + tg    ]);
                    bf[ni][1] = f2tf32(Bs[cur][cc][kk * 8 + tg + 4]);
                } else {
                    bf[ni][0] = f2tf32(Bs[cur][kk * 8 + tg    ][cc]);
                    bf[ni][1] = f2tf32(Bs[cur][kk * 8 + tg + 4][cc]);
                }
            }
            #pragma unroll
            for (int mi = 0; mi < MI; mi++)
                #pragma unroll
                for (int ni = 0; ni < NI; ni++)
                    mma_tf32(acc[mi][ni], af[mi], bf[ni]);
        }
        __syncthreads();
    }

    // ---- epilogue ----
    #pragma unroll
    for (int mi = 0; mi < MI; mi++) {
        #pragma unroll
        for (int ni = 0; ni < NI; ni++) {
            #pragma unroll
            for (int half = 0; half < 2; half++) {
                int m = m0 + wm + mi * 16 + g + half * 8;
                float v0 = acc[mi][ni][half * 2 + 0];
                float v1 = acc[mi][ni][half * 2 + 1];
                int n = n0 + wn + ni * 8 + tg * 2;
                #pragma unroll
                for (int e = 0; e < 2; e++) {
                    float v = e ? v1 : v0;
                    int nn = n + e;
                    if (EPI == 0) {
                        C[z * bC + (size_t)m * N + nn] = v;
                    } else if (EPI == 2) {
                        C[(size_t)m * N + nn] = v + bias[nn] + res[(size_t)m * N + nn];
                    } else if (EPI == 3) {
                        float t = v + bias[nn];
                        C[(size_t)m * N + nn] =
                            0.5f * t * (1.f + erff(t * 0.70710678118654752f));
                    } else if (EPI == 4) {
                        int bb = (int)(z / Hh), hh = (int)(z % Hh);
                        C[((size_t)bb * SEQm + m) * Dm + hh * HDm + nn] = v;
                    } else if (EPI == 5) {
                        int which = nn >> 10;
                        int r = nn & 1023;
                        int hh = r >> 6, hd = r & 63;
                        int bb = m >> 10, t = m & 1023;
                        size_t dst = (((size_t)bb * Hh + hh) * SEQm + t) * HDm + hd;
                        if (which == 0)      g_q[dst] = (v + bias[r]) * 0.125f;
                        else if (which == 1) g_k[dst] = v;
                        else                 g_v[dst] = v + res[r];
                    }
                }
            }
        }
    }
}

// ---------------------------------------------------------------------------
extern "C" void kernel_launch(void* const* d_in, const int* in_sizes, int n_in,
                              void* d_out, int out_size)
{
    const float* x      = (const float*)d_in[0];
    const float* ln1_g  = (const float*)d_in[1];
    const float* ln1_b  = (const float*)d_in[2];
    const float* ln2_g  = (const float*)d_in[3];
    const float* ln2_b  = (const float*)d_in[4];
    const float* qkv_w  = (const float*)d_in[5];
    const float* q_bias = (const float*)d_in[6];
    const float* v_bias = (const float*)d_in[7];
    const float* proj_w = (const float*)d_in[8];
    const float* proj_b = (const float*)d_in[9];
    const float* fc1_w  = (const float*)d_in[10];
    const float* fc1_b  = (const float*)d_in[11];
    const float* fc2_w  = (const float*)d_in[12];
    const float* fc2_b  = (const float*)d_in[13];
    float* out = (float*)d_out;

    float *h, *q, *k, *v, *s, *o, *x1, *g;
    cudaGetSymbolAddress((void**)&h,  g_h);
    cudaGetSymbolAddress((void**)&q,  g_q);
    cudaGetSymbolAddress((void**)&k,  g_k);
    cudaGetSymbolAddress((void**)&v,  g_v);
    cudaGetSymbolAddress((void**)&s,  g_s);
    cudaGetSymbolAddress((void**)&o,  g_o);
    cudaGetSymbolAddress((void**)&x1, g_x1);
    cudaGetSymbolAddress((void**)&g,  g_g);

    // 1. LN1
    ln_kernel<<<TOKm, 256>>>(x, ln1_g, ln1_b, h);

    // 2. QKV = h @ qkv_w^T, fused scatter to q/k/v [B,H,N,HD] + biases + q-scale
    tgemm<128,128,16,64,32,true,5><<<dim3(3072/128, TOKm/128, 1), 256>>>(
        h, qkv_w, nullptr, TOKm, 3*Dm, Dm, 0, 0, 0, q_bias, v_bias);

    // 3. scores[bh] = q[bh] @ k[bh]^T   (K=64)
    tgemm<128,128,16,64,32,true,0><<<dim3(SEQm/128, SEQm/128, BHm), 256>>>(
        q, k, s, SEQm, SEQm, HDm,
        (long)SEQm*HDm, (long)SEQm*HDm, (long)SEQm*SEQm, nullptr, nullptr);

    // 4. softmax rows
    softmax_kernel<<<BHm * SEQm, 256>>>(s);

    // 5. o[bh] = attn[bh] @ v[bh]  (NN, N=64), scatter store to [b,t,h,hd]
    tgemm<128,64,16,32,32,false,4><<<dim3(1, SEQm/128, BHm), 256>>>(
        s, v, o, SEQm, HDm, SEQm,
        (long)SEQm*SEQm, (long)SEQm*HDm, 0, nullptr, nullptr);

    // 6. x1 = x + o @ proj_w^T + proj_b
    tgemm<128,128,16,64,32,true,2><<<dim3(Dm/128, TOKm/128, 1), 256>>>(
        o, proj_w, x1, TOKm, Dm, Dm, 0, 0, 0, proj_b, x);

    // 7. LN2
    ln_kernel<<<TOKm, 256>>>(x1, ln2_g, ln2_b, h);

    // 8. g = gelu(h @ fc1_w^T + fc1_b)
    tgemm<128,128,16,64,32,true,3><<<dim3(FFm/128, TOKm/128, 1), 256>>>(
        h, fc1_w, g, TOKm, FFm, Dm, 0, 0, 0, fc1_b, nullptr);

    // 9. out = x1 + g @ fc2_w^T + fc2_b
    tgemm<128,128,16,64,32,true,2><<<dim3(Dm/128, TOKm/128, 1), 256>>>(
        g, fc2_w, out, TOKm, Dm, FFm, 0, 0, 0, fc2_b, x1);
}